// round 7
// baseline (speedup 1.0000x reference)
#include <cuda_runtime.h>
#include <cuda_bf16.h>
#include <cstdint>

// ---------------- problem constants ----------------
#define B       2
#define T       32768
#define BT      (B*T)           // 65536
#define R2      16384
#define POOL_N  (3*B*R2*128)    // 12,582,912 floats
#define CNT_N   (3*B*R2)

// ---------------- scratch (device globals; no allocs) ----------------
__device__ float g_dx[BT*128];
__device__ float g_h[BT*128];
__device__ float g_net[BT*128];
__device__ float g_poolA[POOL_N];
__device__ float g_poolB[POOL_N];
__device__ float g_cnt[CNT_N];
__device__ int   g_idx[3][BT];
__device__ __nv_bfloat16 g_wt[851968];

// ---------------- helpers ----------------
__device__ __forceinline__ uint32_t smem_u32(const void* p) {
    uint32_t a;
    asm("{ .reg .u64 t; cvta.to.shared.u64 t, %1; cvt.u32.u64 %0, t; }" : "=r"(a) : "l"(p));
    return a;
}
__device__ __forceinline__ void ldsm4(uint32_t& r0, uint32_t& r1, uint32_t& r2, uint32_t& r3,
                                      uint32_t a) {
    asm volatile("ldmatrix.sync.aligned.m8n8.x4.shared.b16 {%0,%1,%2,%3}, [%4];"
        : "=r"(r0), "=r"(r1), "=r"(r2), "=r"(r3) : "r"(a));
}
__device__ __forceinline__ void mma16816(float* c, const uint32_t* a, uint32_t b0, uint32_t b1) {
    asm volatile("mma.sync.aligned.m16n8k16.row.col.f32.bf16.bf16.f32 "
        "{%0,%1,%2,%3}, {%4,%5,%6,%7}, {%8,%9}, {%0,%1,%2,%3};"
        : "+f"(c[0]), "+f"(c[1]), "+f"(c[2]), "+f"(c[3])
        : "r"(a[0]), "r"(a[1]), "r"(a[2]), "r"(a[3]), "r"(b0), "r"(b1));
}
__device__ __forceinline__ uint32_t b2u(__nv_bfloat162 v) {
    return *reinterpret_cast<uint32_t*>(&v);
}
__device__ __forceinline__ void amax(float* addr, float v) {
    if (v >= 0.0f) atomicMax((int*)addr, __float_as_int(v));
    else           atomicMin((unsigned int*)addr, __float_as_uint(v));
}
__device__ __forceinline__ void cp16(uint32_t dst, const void* src) {
    asm volatile("cp.async.ca.shared.global [%0], [%1], 16;" :: "r"(dst), "l"(src));
}

// ---------------- index computation (matches jax exactly) ----------------
__global__ void k_index(const float* __restrict__ p) {
    int t = blockIdx.x * blockDim.x + threadIdx.x;
    if (t >= BT) return;
    float x = p[t*3+0], y = p[t*3+1], z = p[t*3+2];
    float cu[3] = {x, x, y};
    float cv[3] = {z, y, z};
    const float hi = (float)(1.0 - 1e-5);
    #pragma unroll
    for (int k = 0; k < 3; k++) {
        float u = cu[k] / 1.101f + 0.5f;
        float v = cv[k] / 1.101f + 0.5f;
        u = fminf(fmaxf(u, 0.0f), hi);
        v = fminf(fmaxf(v, 0.0f), hi);
        g_idx[k][t] = (int)(u * 128.0f) + 128 * (int)(v * 128.0f);
    }
}

// ---------------- weight pre-split ----------------
__global__ void k_wsplit(const float* __restrict__ W0, const float* __restrict__ W1,
                         const float* __restrict__ Ws, const float* __restrict__ fcW) {
    int i = blockIdx.x * blockDim.x + threadIdx.x;
    if (i >= 425984) return;
    const float* src; int K, base, e;
    if (i < 163840)       { int blk = i / 32768;            e = i % 32768; K = 256; src = W0 + blk*32768; base = blk*65536; }
    else if (i < 245760)  { int j = i - 163840; int blk = j / 16384; e = j % 16384; K = 128; src = W1 + blk*16384; base = 327680 + blk*32768; }
    else if (i < 409600)  { int j = i - 245760; int blk = j / 32768; e = j % 32768; K = 256; src = Ws + blk*32768; base = 491520 + blk*65536; }
    else                  { e = i - 409600; K = 128; src = fcW; base = 819200; }
    int n = e / K, k = e % K;
    float v = src[(size_t)k * 128 + n];
    __nv_bfloat16 hi = __float2bfloat16(v);
    __nv_bfloat16 lo = __float2bfloat16(v - __bfloat162float(hi));
    g_wt[base + (size_t)n * K + k]           = hi;
    g_wt[base + (size_t)128 * K + n * K + k] = lo;
}

// ---------------- fused bf16-split GEMM, double-buffered pipeline, occ 1 ----
// ASRC: 0 = A1 only; 1 = fcpos on-the-fly; 2 = A1 (k<128) + pool gather (k>=128)
#define SA        72
#define PLANE_B   (128 * SA * 2)           // 18432
#define BUFSET_B  (4 * PLANE_B)            // 73728 (AH, AL, BH, BL)
#define GEMM_SMEM (1024 + 2 * BUFSET_B)    // 148480

template<int NCH, int ASRC, bool RELU_A, bool ADD_D, bool SCATTER, bool SCATSUM, bool WRITE_C>
__global__ __launch_bounds__(256, 1)
void k_gemm_mma(const float* __restrict__ A1, int lda1,
                const float* __restrict__ P,
                const float* __restrict__ fcW,
                const float* __restrict__ fcb,
                const float* __restrict__ poolIn,
                float* __restrict__ poolOut,
                float* __restrict__ cnt,
                const __nv_bfloat16* __restrict__ Whi,
                const __nv_bfloat16* __restrict__ Wlo,
                const float* __restrict__ bias,
                const float* __restrict__ Dres,
                float* __restrict__ C) {
    extern __shared__ __align__(16) char smem[];
    float* biasS = (float*)smem;
    const int tid  = threadIdx.x, lane = tid & 31, wid = tid >> 5;
    const int m0   = blockIdx.x * 128;
    const int wm   = (wid & 3) * 32;
    const int wn   = (wid >> 2) * 64;
    const uint32_t sb = smem_u32(smem);
    const int K = NCH * 64;

    if (tid < 128) biasS[tid] = bias ? bias[tid] : 0.0f;

    float acc[2][8][4] = {};

    const int aRow  = wm + (lane & 15);
    const int aCoff = (lane >> 4) * 8;
    const int bRow  = wn + (lane & 7) + ((lane >> 4) << 3);
    const int bCoff = ((lane >> 3) & 1) * 8;

    // ---- A chunk load into registers (8 float4 per thread)
    auto loadA = [&](int ch, float4* vb) {
        const int K0 = ch * 64;
        #pragma unroll
        for (int j = 0; j < 8; j++) {
            int i = tid + j * 256;
            int r = i >> 4, c4 = (i & 15) << 2;
            int m = m0 + r;
            if (ASRC == 1) {
                float p0 = P[m*3+0], p1 = P[m*3+1], p2 = P[m*3+2];
                int cg = K0 + c4;
                float4 v;
                v.x = fmaf(p0, fcW[cg+0], fmaf(p1, fcW[256+cg+0], fmaf(p2, fcW[512+cg+0], fcb[cg+0])));
                v.y = fmaf(p0, fcW[cg+1], fmaf(p1, fcW[256+cg+1], fmaf(p2, fcW[512+cg+1], fcb[cg+1])));
                v.z = fmaf(p0, fcW[cg+2], fmaf(p1, fcW[256+cg+2], fmaf(p2, fcW[512+cg+2], fcb[cg+2])));
                v.w = fmaf(p0, fcW[cg+3], fmaf(p1, fcW[256+cg+3], fmaf(p2, fcW[512+cg+3], fcb[cg+3])));
                vb[j] = v;
            } else if (ASRC == 2 && K0 >= 128) {
                int b = m >> 15;
                int c0 = (K0 - 128) + c4;
                float4 s; s.x = s.y = s.z = s.w = 0.0f;
                #pragma unroll
                for (int k = 0; k < 3; k++) {
                    int cell = g_idx[k][m];
                    float4 pv = *(const float4*)&poolIn[((size_t)((k*B + b)*R2) + cell)*128 + c0];
                    s.x += pv.x; s.y += pv.y; s.z += pv.z; s.w += pv.w;
                }
                vb[j] = s;
            } else {
                vb[j] = *(const float4*)&A1[(size_t)m * lda1 + K0 + c4];
            }
        }
    };
    // ---- convert + store A regs into buffer set
    auto storeA = [&](int buf, const float4* vb) {
        const uint32_t base = 1024u + (uint32_t)buf * BUFSET_B;
        #pragma unroll
        for (int j = 0; j < 8; j++) {
            int i = tid + j * 256;
            int r = i >> 4, c4 = (i & 15) << 2;
            float4 v = vb[j];
            if (RELU_A) {
                v.x = fmaxf(v.x, 0.f); v.y = fmaxf(v.y, 0.f);
                v.z = fmaxf(v.z, 0.f); v.w = fmaxf(v.w, 0.f);
            }
            __nv_bfloat162 h01, h23, l01, l23;
            h01.x = __float2bfloat16(v.x); h01.y = __float2bfloat16(v.y);
            h23.x = __float2bfloat16(v.z); h23.y = __float2bfloat16(v.w);
            l01.x = __float2bfloat16(v.x - __bfloat162float(h01.x));
            l01.y = __float2bfloat16(v.y - __bfloat162float(h01.y));
            l23.x = __float2bfloat16(v.z - __bfloat162float(h23.x));
            l23.y = __float2bfloat16(v.w - __bfloat162float(h23.y));
            uint32_t off = base + (uint32_t)r * (SA*2) + (uint32_t)c4 * 2;
            uint2 hp; hp.x = b2u(h01); hp.y = b2u(h23);
            uint2 lp; lp.x = b2u(l01); lp.y = b2u(l23);
            *(uint2*)(smem + off)           = hp;
            *(uint2*)(smem + off + PLANE_B) = lp;
        }
    };
    // ---- B chunk via cp.async into buffer set
    auto issueB = [&](int ch, int buf) {
        const int K0 = ch * 64;
        const uint32_t base = sb + 1024u + (uint32_t)buf * BUFSET_B + 2 * PLANE_B;
        #pragma unroll
        for (int j = 0; j < 4; j++) {
            int i = tid + j * 256;
            int r = i >> 3, c8 = (i & 7) << 3;
            uint32_t off = base + (uint32_t)r * (SA*2) + (uint32_t)c8 * 2;
            cp16(off,           &Whi[(size_t)r * K + K0 + c8]);
            cp16(off + PLANE_B, &Wlo[(size_t)r * K + K0 + c8]);
        }
        asm volatile("cp.async.commit_group;" ::: "memory");
    };

    float4 areg[8];
    loadA(0, areg);
    issueB(0, 0);

    #pragma unroll
    for (int ch = 0; ch < NCH; ch++) {
        const int buf = ch & 1;
        storeA(buf, areg);
        asm volatile("cp.async.wait_group 0;" ::: "memory");
        __syncthreads();
        if (ch + 1 < NCH) {
            issueB(ch + 1, buf ^ 1);
            loadA(ch + 1, areg);
        }
        const uint32_t OA = 1024u + (uint32_t)buf * BUFSET_B;
        const uint32_t OB = OA + 2 * PLANE_B;
        #pragma unroll
        for (int ks = 0; ks < 64; ks += 16) {
            uint32_t ah0[4], ah1[4], al0[4], al1[4];
            {
                uint32_t c0 = (uint32_t)(ks + aCoff) * 2;
                uint32_t r0 = (uint32_t)aRow * (SA*2);
                uint32_t r1 = (uint32_t)(aRow + 16) * (SA*2);
                ldsm4(ah0[0], ah0[1], ah0[2], ah0[3], sb + OA + r0 + c0);
                ldsm4(ah1[0], ah1[1], ah1[2], ah1[3], sb + OA + r1 + c0);
                ldsm4(al0[0], al0[1], al0[2], al0[3], sb + OA + PLANE_B + r0 + c0);
                ldsm4(al1[0], al1[1], al1[2], al1[3], sb + OA + PLANE_B + r1 + c0);
            }
            uint32_t bh[8][2], bl[8][2];
            #pragma unroll
            for (int nf2 = 0; nf2 < 4; nf2++) {
                uint32_t addr = (uint32_t)(bRow + nf2*16) * (SA*2) + (uint32_t)(ks + bCoff) * 2;
                ldsm4(bh[nf2*2][0], bh[nf2*2][1], bh[nf2*2+1][0], bh[nf2*2+1][1],
                      sb + OB + addr);
                ldsm4(bl[nf2*2][0], bl[nf2*2][1], bl[nf2*2+1][0], bl[nf2*2+1][1],
                      sb + OB + PLANE_B + addr);
            }
            #pragma unroll
            for (int nf = 0; nf < 8; nf++) {
                mma16816(acc[0][nf], ah0, bh[nf][0], bh[nf][1]);
                mma16816(acc[1][nf], ah1, bh[nf][0], bh[nf][1]);
                mma16816(acc[0][nf], ah0, bl[nf][0], bl[nf][1]);
                mma16816(acc[1][nf], ah1, bl[nf][0], bl[nf][1]);
                mma16816(acc[0][nf], al0, bh[nf][0], bh[nf][1]);
                mma16816(acc[1][nf], al1, bh[nf][0], bh[nf][1]);
            }
        }
    }

    // ---- epilogue
    #pragma unroll
    for (int mf = 0; mf < 2; mf++) {
        const int m  = m0 + wm + mf*16 + (lane >> 2);
        const int bb = m >> 15;
        int cellA[3], cellB[3];
        if (SCATTER || SCATSUM) {
            #pragma unroll
            for (int k = 0; k < 3; k++) {
                cellA[k] = g_idx[k][m];
                cellB[k] = g_idx[k][m + 8];
            }
        }
        #pragma unroll
        for (int nf = 0; nf < 8; nf++) {
            int n = wn + nf*8 + (lane & 3) * 2;
            float2 v0, v1;
            v0.x = acc[mf][nf][0] + biasS[n];
            v0.y = acc[mf][nf][1] + biasS[n+1];
            v1.x = acc[mf][nf][2] + biasS[n];
            v1.y = acc[mf][nf][3] + biasS[n+1];
            if (ADD_D) {
                float2 d0 = *(const float2*)&Dres[(size_t)m * 128 + n];
                float2 d1 = *(const float2*)&Dres[(size_t)(m+8) * 128 + n];
                v0.x += d0.x; v0.y += d0.y; v1.x += d1.x; v1.y += d1.y;
            }
            if (WRITE_C) {
                *(float2*)&C[(size_t)m * 128 + n]     = v0;
                *(float2*)&C[(size_t)(m+8) * 128 + n] = v1;
            }
            if (SCATTER) {
                #pragma unroll
                for (int k = 0; k < 3; k++) {
                    float* pA = &poolOut[((size_t)((k*B + bb)*R2) + cellA[k])*128 + n];
                    float* pB = &poolOut[((size_t)((k*B + bb)*R2) + cellB[k])*128 + n];
                    amax(pA,     v0.x); amax(pA + 1, v0.y);
                    amax(pB,     v1.x); amax(pB + 1, v1.y);
                }
            }
            if (SCATSUM) {
                #pragma unroll
                for (int k = 0; k < 3; k++) {
                    float* pA = &poolOut[((size_t)((k*B + bb)*R2) + cellA[k])*128 + n];
                    float* pB = &poolOut[((size_t)((k*B + bb)*R2) + cellB[k])*128 + n];
                    atomicAdd(pA,     v0.x); atomicAdd(pA + 1, v0.y);
                    atomicAdd(pB,     v1.x); atomicAdd(pB + 1, v1.y);
                    if (n == 0) {
                        atomicAdd(&cnt[(k*B + bb)*R2 + cellA[k]], 1.0f);
                        atomicAdd(&cnt[(k*B + bb)*R2 + cellB[k]], 1.0f);
                    }
                }
            }
        }
    }
}

// ---------------- utility kernels ----------------
__global__ void k_pool_neg_inf(float* __restrict__ pool) {
    int i = blockIdx.x * blockDim.x + threadIdx.x;
    if (i < POOL_N / 4) {
        int4 v; v.x = v.y = v.z = v.w = 0xFF800000;
        ((int4*)pool)[i] = v;
    }
}

__global__ void k_zero(float* __restrict__ pool) {
    int i = blockIdx.x * blockDim.x + threadIdx.x;
    if (i < POOL_N / 4) {
        float4 z; z.x = z.y = z.z = z.w = 0.0f;
        ((float4*)pool)[i] = z;
    }
    if (i < CNT_N) g_cnt[i] = 0.0f;
}

__global__ void k_finalize(const float* __restrict__ pool, float* __restrict__ out) {
    int i = blockIdx.x * blockDim.x + threadIdx.x;   // [kb][f][cell]
    if (i >= POOL_N) return;
    int cell = i & (R2 - 1);
    int f    = (i >> 14) & 127;
    int kb   = i >> 21;
    float cnt = g_cnt[kb * R2 + cell];
    out[i] = pool[(size_t)(kb * R2 + cell) * 128 + f] / fmaxf(cnt, 1.0f);
}

// ---------------- host orchestration ----------------
extern "C" void kernel_launch(void* const* d_in, const int* in_sizes, int n_in,
                              void* d_out, int out_size) {
    const float* p        = (const float*)d_in[0];
    const float* fc_pos_W = (const float*)d_in[1];
    const float* fc_pos_b = (const float*)d_in[2];
    const float* bW0      = (const float*)d_in[3];
    const float* bb0      = (const float*)d_in[4];
    const float* bW1      = (const float*)d_in[5];
    const float* bb1      = (const float*)d_in[6];
    const float* bWs      = (const float*)d_in[7];
    const float* fc_c_W   = (const float*)d_in[8];
    const float* fc_c_b   = (const float*)d_in[9];
    float* out = (float*)d_out;

    float* gdx  = nullptr; cudaGetSymbolAddress((void**)&gdx,  g_dx);
    float* gh   = nullptr; cudaGetSymbolAddress((void**)&gh,   g_h);
    float* gnet = nullptr; cudaGetSymbolAddress((void**)&gnet, g_net);
    float* pA   = nullptr; cudaGetSymbolAddress((void**)&pA,   g_poolA);
    float* pB   = nullptr; cudaGetSymbolAddress((void**)&pB,   g_poolB);
    float* gcnt = nullptr; cudaGetSymbolAddress((void**)&gcnt, g_cnt);
    __nv_bfloat16* wt = nullptr; cudaGetSymbolAddress((void**)&wt, g_wt);

    auto* gW0f = k_gemm_mma<4, 1, true,  false, false, false, true>;
    auto* gW1  = k_gemm_mma<2, 0, true,  false, false, false, true>;
    auto* gWsf = k_gemm_mma<4, 1, false, true,  true,  false, true>;
    auto* gW0  = k_gemm_mma<4, 2, true,  false, false, false, true>;
    auto* gWsS = k_gemm_mma<4, 2, false, true,  true,  false, true>;
    auto* gWsL = k_gemm_mma<4, 2, false, true,  false, false, true>;
    auto* gFC  = k_gemm_mma<2, 0, false, false, false, true,  false>;

    cudaFuncSetAttribute(gW0f, cudaFuncAttributeMaxDynamicSharedMemorySize, GEMM_SMEM);
    cudaFuncSetAttribute(gW1,  cudaFuncAttributeMaxDynamicSharedMemorySize, GEMM_SMEM);
    cudaFuncSetAttribute(gWsf, cudaFuncAttributeMaxDynamicSharedMemorySize, GEMM_SMEM);
    cudaFuncSetAttribute(gW0,  cudaFuncAttributeMaxDynamicSharedMemorySize, GEMM_SMEM);
    cudaFuncSetAttribute(gWsS, cudaFuncAttributeMaxDynamicSharedMemorySize, GEMM_SMEM);
    cudaFuncSetAttribute(gWsL, cudaFuncAttributeMaxDynamicSharedMemorySize, GEMM_SMEM);
    cudaFuncSetAttribute(gFC,  cudaFuncAttributeMaxDynamicSharedMemorySize, GEMM_SMEM);

    const int TPB = 256;
    const int GG  = BT / 128;   // 512
    const int RG  = POOL_N / 4 / TPB;

    k_index<<<BT / TPB, TPB>>>(p);
    k_wsplit<<<(425984 + TPB - 1) / TPB, TPB>>>(bW0, bW1, bWs, fc_c_W);

    auto W0hi = [&](int b){ return wt + (size_t)b * 65536; };
    auto W0lo = [&](int b){ return wt + (size_t)b * 65536 + 32768; };
    auto W1hi = [&](int b){ return wt + 327680 + (size_t)b * 32768; };
    auto W1lo = [&](int b){ return wt + 327680 + (size_t)b * 32768 + 16384; };
    auto WShi = [&](int b){ return wt + 491520 + (size_t)b * 65536; };
    auto WSlo = [&](int b){ return wt + 491520 + (size_t)b * 65536 + 32768; };
    const __nv_bfloat16* FChi = wt + 819200;
    const __nv_bfloat16* FClo = wt + 819200 + 16384;

    // block 0
    k_pool_neg_inf<<<RG, TPB>>>(pA);
    gW0f<<<GG, TPB, GEMM_SMEM>>>(nullptr, 0, p, fc_pos_W, fc_pos_b, nullptr, nullptr, nullptr,
                                 W0hi(0), W0lo(0), bb0, nullptr, gh);
    gW1 <<<GG, TPB, GEMM_SMEM>>>(gh, 128, nullptr, nullptr, nullptr, nullptr, nullptr, nullptr,
                                 W1hi(0), W1lo(0), bb1, nullptr, gdx);
    gWsf<<<GG, TPB, GEMM_SMEM>>>(nullptr, 0, p, fc_pos_W, fc_pos_b, nullptr, pA, nullptr,
                                 WShi(0), WSlo(0), nullptr, gdx, gnet);

    // blocks 1..4 (ping-pong pools)
    float* pin  = pA;
    float* pout = pB;
    for (int blk = 1; blk < 5; blk++) {
        if (blk < 4) k_pool_neg_inf<<<RG, TPB>>>(pout);
        gW0<<<GG, TPB, GEMM_SMEM>>>(gnet, 128, nullptr, nullptr, nullptr, pin, nullptr, nullptr,
                                    W0hi(blk), W0lo(blk), bb0 + blk*128, nullptr, gh);
        gW1<<<GG, TPB, GEMM_SMEM>>>(gh, 128, nullptr, nullptr, nullptr, nullptr, nullptr, nullptr,
                                    W1hi(blk), W1lo(blk), bb1 + blk*128, nullptr, gdx);
        if (blk < 4) {
            gWsS<<<GG, TPB, GEMM_SMEM>>>(gnet, 128, nullptr, nullptr, nullptr, pin, pout, nullptr,
                                         WShi(blk), WSlo(blk), nullptr, gdx, gnet);
        } else {
            gWsL<<<GG, TPB, GEMM_SMEM>>>(gnet, 128, nullptr, nullptr, nullptr, pin, nullptr, nullptr,
                                         WShi(blk), WSlo(blk), nullptr, gdx, gnet);
        }
        float* tmp = pin; pin = pout; pout = tmp;
    }

    // fc_c with fused scatter-mean into poolA
    k_zero<<<RG, TPB>>>(pA);
    gFC<<<GG, TPB, GEMM_SMEM>>>(gnet, 128, nullptr, nullptr, nullptr, nullptr, pA, gcnt,
                                FChi, FClo, fc_c_b, nullptr, nullptr);

    k_finalize<<<(POOL_N + TPB - 1) / TPB, TPB>>>(pA, out);
}

// round 8
// speedup vs baseline: 1.1986x; 1.1986x over previous
#include <cuda_runtime.h>
#include <cuda_bf16.h>
#include <cstdint>

// ---------------- problem constants ----------------
#define B       2
#define T       32768
#define BT      (B*T)           // 65536
#define R2      16384
#define POOL_N  (3*B*R2*128)
#define CNT_N   (3*B*R2)

// ---------------- scratch ----------------
__device__ float g_net[BT*128];
__device__ float g_poolA[POOL_N];
__device__ float g_poolB[POOL_N];
__device__ float g_cnt[CNT_N];
__device__ int   g_idx[3][BT];
__device__ __nv_bfloat16 g_wt[851968];

// ---------------- helpers ----------------
__device__ __forceinline__ uint32_t smem_u32(const void* p) {
    uint32_t a;
    asm("{ .reg .u64 t; cvta.to.shared.u64 t, %1; cvt.u32.u64 %0, t; }" : "=r"(a) : "l"(p));
    return a;
}
__device__ __forceinline__ void ldsm4(uint32_t& r0, uint32_t& r1, uint32_t& r2, uint32_t& r3,
                                      uint32_t a) {
    asm volatile("ldmatrix.sync.aligned.m8n8.x4.shared.b16 {%0,%1,%2,%3}, [%4];"
        : "=r"(r0), "=r"(r1), "=r"(r2), "=r"(r3) : "r"(a));
}
__device__ __forceinline__ void mma16816(float* c, const uint32_t* a, uint32_t b0, uint32_t b1) {
    asm volatile("mma.sync.aligned.m16n8k16.row.col.f32.bf16.bf16.f32 "
        "{%0,%1,%2,%3}, {%4,%5,%6,%7}, {%8,%9}, {%0,%1,%2,%3};"
        : "+f"(c[0]), "+f"(c[1]), "+f"(c[2]), "+f"(c[3])
        : "r"(a[0]), "r"(a[1]), "r"(a[2]), "r"(a[3]), "r"(b0), "r"(b1));
}
__device__ __forceinline__ uint32_t b2u(__nv_bfloat162 v) {
    return *reinterpret_cast<uint32_t*>(&v);
}
__device__ __forceinline__ void amax(float* addr, float v) {
    if (v >= 0.0f) atomicMax((int*)addr, __float_as_int(v));
    else           atomicMin((unsigned int*)addr, __float_as_uint(v));
}
__device__ __forceinline__ void cp16(uint32_t dst, const void* src) {
    asm volatile("cp.async.ca.shared.global [%0], [%1], 16;" :: "r"(dst), "l"(src));
}
// 128B-row swizzle: 16B chunk index XOR (row&7)
__device__ __forceinline__ uint32_t sw(int r, int cb) {
    return (uint32_t)(r * 128 + ((((cb >> 4) ^ (r & 7)) & 7) << 4) + (cb & 15));
}

// ---------------- index computation ----------------
__global__ void k_index(const float* __restrict__ p) {
    int t = blockIdx.x * blockDim.x + threadIdx.x;
    if (t >= BT) return;
    float x = p[t*3+0], y = p[t*3+1], z = p[t*3+2];
    float cu[3] = {x, x, y};
    float cv[3] = {z, y, z};
    const float hi = (float)(1.0 - 1e-5);
    #pragma unroll
    for (int k = 0; k < 3; k++) {
        float u = cu[k] / 1.101f + 0.5f;
        float v = cv[k] / 1.101f + 0.5f;
        u = fminf(fmaxf(u, 0.0f), hi);
        v = fminf(fmaxf(v, 0.0f), hi);
        g_idx[k][t] = (int)(u * 128.0f) + 128 * (int)(v * 128.0f);
    }
}

// ---------------- weight pre-split ----------------
__global__ void k_wsplit(const float* __restrict__ W0, const float* __restrict__ W1,
                         const float* __restrict__ Ws, const float* __restrict__ fcW) {
    int i = blockIdx.x * blockDim.x + threadIdx.x;
    if (i >= 425984) return;
    const float* src; int K, base, e;
    if (i < 163840)       { int blk = i / 32768;            e = i % 32768; K = 256; src = W0 + blk*32768; base = blk*65536; }
    else if (i < 245760)  { int j = i - 163840; int blk = j / 16384; e = j % 16384; K = 128; src = W1 + blk*16384; base = 327680 + blk*32768; }
    else if (i < 409600)  { int j = i - 245760; int blk = j / 32768; e = j % 32768; K = 256; src = Ws + blk*32768; base = 491520 + blk*65536; }
    else                  { e = i - 409600; K = 128; src = fcW; base = 819200; }
    int n = e / K, k = e % K;
    float v = src[(size_t)k * 128 + n];
    __nv_bfloat16 hi = __float2bfloat16(v);
    __nv_bfloat16 lo = __float2bfloat16(v - __bfloat162float(hi));
    g_wt[base + (size_t)n * K + k]           = hi;
    g_wt[base + (size_t)128 * K + n * K + k] = lo;
}

// =====================================================================
// Fused ResNet-block kernel: W0 -> W1 (SMEM hidden) -> Ws (+scatter)
// SMEM layout (swizzled 128B-row planes of 16KB):
//  [0..512)  b0S   [512..1024) b1S
//  set(s) at 1024 + s*64KB : AH, AL, BH, BL planes
//  hidden at 132096 : ch0{HH,HL}, ch1{HH,HL}
// =====================================================================
#define PLANE   16384
#define SETSZ   (4*PLANE)
#define SOFF    1024u
#define HIDOFF  (SOFF + 2*SETSZ)                 // 132096
#define FSMEM   (HIDOFF + 4*PLANE)               // 197632

template<int ASRC, bool SCATTER>
__global__ __launch_bounds__(256, 1)
void k_block(const float* __restrict__ A1,        // gnet (ASRC2)
             const float* __restrict__ P,         // points (ASRC1)
             const float* __restrict__ fcW,
             const float* __restrict__ fcb,
             const float* __restrict__ poolIn,    // (ASRC2)
             float* __restrict__ poolOut,
             const __nv_bfloat16* __restrict__ W0hi, const __nv_bfloat16* __restrict__ W0lo,
             const __nv_bfloat16* __restrict__ W1hi, const __nv_bfloat16* __restrict__ W1lo,
             const __nv_bfloat16* __restrict__ WShi, const __nv_bfloat16* __restrict__ WSlo,
             const float* __restrict__ b0, const float* __restrict__ b1,
             float* __restrict__ C) {
    extern __shared__ __align__(16) char smem[];
    float* b0S = (float*)smem;
    float* b1S = (float*)(smem + 512);
    const int tid  = threadIdx.x, lane = tid & 31, wid = tid >> 5;
    const int m0   = blockIdx.x * 128;
    const int wm   = (wid & 3) * 32;
    const int wn   = (wid >> 2) * 64;
    const uint32_t sb = smem_u32(smem);

    if (tid < 128) { b0S[tid] = b0[tid]; b1S[tid] = b1[tid]; }

    const int aRow  = wm + (lane & 15);
    const int aCoff = (lane >> 4) * 8;
    const int bRow  = wn + (lane & 7) + ((lane >> 4) << 3);
    const int bCoff = ((lane >> 3) & 1) * 8;

    float acc[2][8][4] = {};

    // ---- A chunk (64 k) load into regs; source per ASRC
    auto loadA = [&](int ch, float4* vb) {
        const int K0 = ch * 64;
        #pragma unroll
        for (int j = 0; j < 8; j++) {
            int i = tid + j * 256;
            int r = i >> 4, c4 = (i & 15) << 2;
            int m = m0 + r;
            if (ASRC == 1) {
                float p0 = P[m*3+0], p1 = P[m*3+1], p2 = P[m*3+2];
                int cg = K0 + c4;
                float4 v;
                v.x = fmaf(p0, fcW[cg+0], fmaf(p1, fcW[256+cg+0], fmaf(p2, fcW[512+cg+0], fcb[cg+0])));
                v.y = fmaf(p0, fcW[cg+1], fmaf(p1, fcW[256+cg+1], fmaf(p2, fcW[512+cg+1], fcb[cg+1])));
                v.z = fmaf(p0, fcW[cg+2], fmaf(p1, fcW[256+cg+2], fmaf(p2, fcW[512+cg+2], fcb[cg+2])));
                v.w = fmaf(p0, fcW[cg+3], fmaf(p1, fcW[256+cg+3], fmaf(p2, fcW[512+cg+3], fcb[cg+3])));
                vb[j] = v;
            } else if (K0 >= 128) {
                int b = m >> 15;
                int c0 = (K0 - 128) + c4;
                float4 s; s.x = s.y = s.z = s.w = 0.0f;
                #pragma unroll
                for (int k = 0; k < 3; k++) {
                    int cell = g_idx[k][m];
                    float4 pv = *(const float4*)&poolIn[((size_t)((k*B + b)*R2) + cell)*128 + c0];
                    s.x += pv.x; s.y += pv.y; s.z += pv.z; s.w += pv.w;
                }
                vb[j] = s;
            } else {
                vb[j] = *(const float4*)&A1[(size_t)m * 128 + K0 + c4];
            }
        }
    };
    auto storeA = [&](int set, const float4* vb, bool relu) {
        const uint32_t base = SOFF + (uint32_t)set * SETSZ;
        #pragma unroll
        for (int j = 0; j < 8; j++) {
            int i = tid + j * 256;
            int r = i >> 4, c4 = (i & 15) << 2;
            float4 v = vb[j];
            if (relu) {
                v.x = fmaxf(v.x, 0.f); v.y = fmaxf(v.y, 0.f);
                v.z = fmaxf(v.z, 0.f); v.w = fmaxf(v.w, 0.f);
            }
            __nv_bfloat162 h01, h23, l01, l23;
            h01.x = __float2bfloat16(v.x); h01.y = __float2bfloat16(v.y);
            h23.x = __float2bfloat16(v.z); h23.y = __float2bfloat16(v.w);
            l01.x = __float2bfloat16(v.x - __bfloat162float(h01.x));
            l01.y = __float2bfloat16(v.y - __bfloat162float(h01.y));
            l23.x = __float2bfloat16(v.z - __bfloat162float(h23.x));
            l23.y = __float2bfloat16(v.w - __bfloat162float(h23.y));
            uint32_t off = sw(r, c4 * 2);
            *(uint2*)(smem + base + off)         = make_uint2(b2u(h01), b2u(h23));
            *(uint2*)(smem + base + PLANE + off) = make_uint2(b2u(l01), b2u(l23));
        }
    };
    auto cpB = [&](const __nv_bfloat16* Whi, const __nv_bfloat16* Wlo, int K, int ch, int set) {
        const int K0 = ch * 64;
        const uint32_t base = sb + SOFF + (uint32_t)set * SETSZ + 2 * PLANE;
        #pragma unroll
        for (int j = 0; j < 4; j++) {
            int i = tid + j * 256;
            int r = i >> 3, c8 = (i & 7) << 3;
            uint32_t off = sw(r, c8 * 2);
            cp16(base + off,         &Whi[(size_t)r * K + K0 + c8]);
            cp16(base + PLANE + off, &Wlo[(size_t)r * K + K0 + c8]);
        }
        asm volatile("cp.async.commit_group;" ::: "memory");
    };
    // ---- MMA over one 64-k chunk; A planes at aBase(H/L), B planes at bBase(H/L)
    auto mmaChunk = [&](uint32_t aBase, uint32_t bBase) {
        #pragma unroll
        for (int ks = 0; ks < 64; ks += 16) {
            uint32_t ah0[4], ah1[4], al0[4], al1[4];
            {
                uint32_t c0 = (uint32_t)((ks + aCoff) * 2);
                ldsm4(ah0[0], ah0[1], ah0[2], ah0[3], sb + aBase + sw(aRow,      c0));
                ldsm4(ah1[0], ah1[1], ah1[2], ah1[3], sb + aBase + sw(aRow + 16, c0));
                ldsm4(al0[0], al0[1], al0[2], al0[3], sb + aBase + PLANE + sw(aRow,      c0));
                ldsm4(al1[0], al1[1], al1[2], al1[3], sb + aBase + PLANE + sw(aRow + 16, c0));
            }
            uint32_t bh[8][2], bl[8][2];
            #pragma unroll
            for (int nf2 = 0; nf2 < 4; nf2++) {
                uint32_t c0 = (uint32_t)((ks + bCoff) * 2);
                uint32_t ad = sw(bRow + nf2*16, c0);
                ldsm4(bh[nf2*2][0], bh[nf2*2][1], bh[nf2*2+1][0], bh[nf2*2+1][1], sb + bBase + ad);
                ldsm4(bl[nf2*2][0], bl[nf2*2][1], bl[nf2*2+1][0], bl[nf2*2+1][1], sb + bBase + PLANE + ad);
            }
            #pragma unroll
            for (int nf = 0; nf < 8; nf++) {
                mma16816(acc[0][nf], ah0, bh[nf][0], bh[nf][1]);
                mma16816(acc[1][nf], ah1, bh[nf][0], bh[nf][1]);
                mma16816(acc[0][nf], ah0, bl[nf][0], bl[nf][1]);
                mma16816(acc[1][nf], ah1, bl[nf][0], bl[nf][1]);
                mma16816(acc[0][nf], al0, bh[nf][0], bh[nf][1]);
                mma16816(acc[1][nf], al1, bh[nf][0], bh[nf][1]);
            }
        }
    };

    // ================= phase W0 (K=256, relu A) =================
    float4 areg[8];
    loadA(0, areg);
    cpB(W0hi, W0lo, 256, 0, 0);
    #pragma unroll
    for (int ch = 0; ch < 4; ch++) {
        const int set = ch & 1;
        storeA(set, areg, true);
        asm volatile("cp.async.wait_group 0;" ::: "memory");
        __syncthreads();
        if (ch < 3) {
            cpB(W0hi, W0lo, 256, ch + 1, set ^ 1);
            loadA(ch + 1, areg);
        } else {
            cpB(W1hi, W1lo, 128, 0, 0);   // W1 ch0 -> set0 B (set0 B free after MMA(2))
        }
        mmaChunk(SOFF + (uint32_t)set * SETSZ, SOFF + (uint32_t)set * SETSZ + 2*PLANE);
    }
    __syncthreads();   // all warps done W0 MMA (set1 B free)
    cpB(W1hi, W1lo, 128, 1, 1);
    loadA(0, areg);    // prefetch Ws A chunk0 (raw)

    // hidden = relu(acc + b0) -> hidden planes; then acc = b1
    #pragma unroll
    for (int mf = 0; mf < 2; mf++) {
        int mloc = wm + mf*16 + (lane >> 2);
        #pragma unroll
        for (int nf = 0; nf < 8; nf++) {
            int n = wn + nf*8 + (lane & 3) * 2;
            int hc = n >> 6;
            uint32_t hb = HIDOFF + (uint32_t)hc * 2 * PLANE;
            #pragma unroll
            for (int q = 0; q < 2; q++) {     // q0: row mloc, q1: row mloc+8
                int r = mloc + q * 8;
                float h0 = fmaxf(acc[mf][nf][2*q]   + b0S[n],   0.0f);
                float h1 = fmaxf(acc[mf][nf][2*q+1] + b0S[n+1], 0.0f);
                __nv_bfloat162 hh, ll;
                hh.x = __float2bfloat16(h0); hh.y = __float2bfloat16(h1);
                ll.x = __float2bfloat16(h0 - __bfloat162float(hh.x));
                ll.y = __float2bfloat16(h1 - __bfloat162float(hh.y));
                uint32_t off = sw(r, (n & 63) * 2);
                *(uint32_t*)(smem + hb + off)         = b2u(hh);
                *(uint32_t*)(smem + hb + PLANE + off) = b2u(ll);
            }
            #pragma unroll
            for (int q = 0; q < 4; q++) acc[mf][nf][q] = b1S[n + (q & 1)];
        }
    }
    asm volatile("cp.async.wait_group 0;" ::: "memory");
    __syncthreads();   // hidden visible + W1 B loaded

    // ================= phase W1 (K=128, A = hidden planes) =================
    mmaChunk(HIDOFF,             SOFF + 2*PLANE);            // ch0: hidden0, set0 B
    mmaChunk(HIDOFF + 2*PLANE,   SOFF + SETSZ + 2*PLANE);    // ch1: hidden1, set1 B
    __syncthreads();   // B planes free

    // ================= phase Ws (K=256, raw A), acc carries dx+b1 =================
    cpB(WShi, WSlo, 256, 0, 0);
    #pragma unroll
    for (int ch = 0; ch < 4; ch++) {
        const int set = ch & 1;
        storeA(set, areg, false);
        asm volatile("cp.async.wait_group 0;" ::: "memory");
        __syncthreads();
        if (ch < 3) {
            cpB(WShi, WSlo, 256, ch + 1, set ^ 1);
            loadA(ch + 1, areg);
        }
        mmaChunk(SOFF + (uint32_t)set * SETSZ, SOFF + (uint32_t)set * SETSZ + 2*PLANE);
    }

    // ---- epilogue: write net (+ scatter-max)
    #pragma unroll
    for (int mf = 0; mf < 2; mf++) {
        const int m  = m0 + wm + mf*16 + (lane >> 2);
        const int bb = m >> 15;
        int cellA[3], cellB[3];
        if (SCATTER) {
            #pragma unroll
            for (int k = 0; k < 3; k++) {
                cellA[k] = g_idx[k][m];
                cellB[k] = g_idx[k][m + 8];
            }
        }
        #pragma unroll
        for (int nf = 0; nf < 8; nf++) {
            int n = wn + nf*8 + (lane & 3) * 2;
            float2 v0, v1;
            v0.x = acc[mf][nf][0]; v0.y = acc[mf][nf][1];
            v1.x = acc[mf][nf][2]; v1.y = acc[mf][nf][3];
            *(float2*)&C[(size_t)m * 128 + n]     = v0;
            *(float2*)&C[(size_t)(m+8) * 128 + n] = v1;
            if (SCATTER) {
                #pragma unroll
                for (int k = 0; k < 3; k++) {
                    float* pA = &poolOut[((size_t)((k*B + bb)*R2) + cellA[k])*128 + n];
                    float* pB = &poolOut[((size_t)((k*B + bb)*R2) + cellB[k])*128 + n];
                    amax(pA,     v0.x); amax(pA + 1, v0.y);
                    amax(pB,     v1.x); amax(pB + 1, v1.y);
                }
            }
        }
    }
}

// =====================================================================
// fc_c GEMM (K=128) with fused scatter-sum (R7-style pipeline)
// =====================================================================
#define FC_SMEM (1024 + 2 * 4 * PLANE)   // 132096

__global__ __launch_bounds__(256, 1)
void k_fcc(const float* __restrict__ A1,
           float* __restrict__ poolOut, float* __restrict__ cnt,
           const __nv_bfloat16* __restrict__ Whi, const __nv_bfloat16* __restrict__ Wlo,
           const float* __restrict__ bias) {
    extern __shared__ __align__(16) char smem[];
    float* biasS = (float*)smem;
    const int tid  = threadIdx.x, lane = tid & 31, wid = tid >> 5;
    const int m0   = blockIdx.x * 128;
    const int wm   = (wid & 3) * 32;
    const int wn   = (wid >> 2) * 64;
    const uint32_t sb = smem_u32(smem);

    if (tid < 128) biasS[tid] = bias[tid];

    const int aRow  = wm + (lane & 15);
    const int aCoff = (lane >> 4) * 8;
    const int bRow  = wn + (lane & 7) + ((lane >> 4) << 3);
    const int bCoff = ((lane >> 3) & 1) * 8;

    float acc[2][8][4] = {};

    auto loadA = [&](int ch, float4* vb) {
        #pragma unroll
        for (int j = 0; j < 8; j++) {
            int i = tid + j * 256;
            int r = i >> 4, c4 = (i & 15) << 2;
            vb[j] = *(const float4*)&A1[(size_t)(m0 + r) * 128 + ch * 64 + c4];
        }
    };
    auto storeA = [&](int set, const float4* vb) {
        const uint32_t base = SOFF + (uint32_t)set * SETSZ;
        #pragma unroll
        for (int j = 0; j < 8; j++) {
            int i = tid + j * 256;
            int r = i >> 4, c4 = (i & 15) << 2;
            float4 v = vb[j];
            __nv_bfloat162 h01, h23, l01, l23;
            h01.x = __float2bfloat16(v.x); h01.y = __float2bfloat16(v.y);
            h23.x = __float2bfloat16(v.z); h23.y = __float2bfloat16(v.w);
            l01.x = __float2bfloat16(v.x - __bfloat162float(h01.x));
            l01.y = __float2bfloat16(v.y - __bfloat162float(h01.y));
            l23.x = __float2bfloat16(v.z - __bfloat162float(h23.x));
            l23.y = __float2bfloat16(v.w - __bfloat162float(h23.y));
            uint32_t off = sw(r, c4 * 2);
            *(uint2*)(smem + base + off)         = make_uint2(b2u(h01), b2u(h23));
            *(uint2*)(smem + base + PLANE + off) = make_uint2(b2u(l01), b2u(l23));
        }
    };
    auto cpB = [&](int ch, int set) {
        const uint32_t base = sb + SOFF + (uint32_t)set * SETSZ + 2 * PLANE;
        #pragma unroll
        for (int j = 0; j < 4; j++) {
            int i = tid + j * 256;
            int r = i >> 3, c8 = (i & 7) << 3;
            uint32_t off = sw(r, c8 * 2);
            cp16(base + off,         &Whi[(size_t)r * 128 + ch * 64 + c8]);
            cp16(base + PLANE + off, &Wlo[(size_t)r * 128 + ch * 64 + c8]);
        }
        asm volatile("cp.async.commit_group;" ::: "memory");
    };
    auto mmaChunk = [&](uint32_t aBase, uint32_t bBase) {
        #pragma unroll
        for (int ks = 0; ks < 64; ks += 16) {
            uint32_t ah0[4], ah1[4], al0[4], al1[4];
            uint32_t c0 = (uint32_t)((ks + aCoff) * 2);
            ldsm4(ah0[0], ah0[1], ah0[2], ah0[3], sb + aBase + sw(aRow,      c0));
            ldsm4(ah1[0], ah1[1], ah1[2], ah1[3], sb + aBase + sw(aRow + 16, c0));
            ldsm4(al0[0], al0[1], al0[2], al0[3], sb + aBase + PLANE + sw(aRow,      c0));
            ldsm4(al1[0], al1[1], al1[2], al1[3], sb + aBase + PLANE + sw(aRow + 16, c0));
            uint32_t bh[8][2], bl[8][2];
            #pragma unroll
            for (int nf2 = 0; nf2 < 4; nf2++) {
                uint32_t ad = sw(bRow + nf2*16, (uint32_t)((ks + bCoff) * 2));
                ldsm4(bh[nf2*2][0], bh[nf2*2][1], bh[nf2*2+1][0], bh[nf2*2+1][1], sb + bBase + ad);
                ldsm4(bl[nf2*2][0], bl[nf2*2][1], bl[nf2*2+1][0], bl[nf2*2+1][1], sb + bBase + PLANE + ad);
            }
            #pragma unroll
            for (int nf = 0; nf < 8; nf++) {
                mma16816(acc[0][nf], ah0, bh[nf][0], bh[nf][1]);
                mma16816(acc[1][nf], ah1, bh[nf][0], bh[nf][1]);
                mma16816(acc[0][nf], ah0, bl[nf][0], bl[nf][1]);
                mma16816(acc[1][nf], ah1, bl[nf][0], bl[nf][1]);
                mma16816(acc[0][nf], al0, bh[nf][0], bh[nf][1]);
                mma16816(acc[1][nf], al1, bh[nf][0], bh[nf][1]);
            }
        }
    };

    float4 areg[8];
    loadA(0, areg);
    cpB(0, 0);
    #pragma unroll
    for (int ch = 0; ch < 2; ch++) {
        const int set = ch & 1;
        storeA(set, areg);
        asm volatile("cp.async.wait_group 0;" ::: "memory");
        __syncthreads();
        if (ch < 1) { cpB(1, 1); loadA(1, areg); }
        mmaChunk(SOFF + (uint32_t)set * SETSZ, SOFF + (uint32_t)set * SETSZ + 2*PLANE);
    }

    // epilogue: scatter-sum only
    #pragma unroll
    for (int mf = 0; mf < 2; mf++) {
        const int m  = m0 + wm + mf*16 + (lane >> 2);
        const int bb = m >> 15;
        int cellA[3], cellB[3];
        #pragma unroll
        for (int k = 0; k < 3; k++) {
            cellA[k] = g_idx[k][m];
            cellB[k] = g_idx[k][m + 8];
        }
        #pragma unroll
        for (int nf = 0; nf < 8; nf++) {
            int n = wn + nf*8 + (lane & 3) * 2;
            float2 v0, v1;
            v0.x = acc[mf][nf][0] + biasS[n];
            v0.y = acc[mf][nf][1] + biasS[n+1];
            v1.x = acc[mf][nf][2] + biasS[n];
            v1.y = acc[mf][nf][3] + biasS[n+1];
            #pragma unroll
            for (int k = 0; k < 3; k++) {
                float* pA = &poolOut[((size_t)((k*B + bb)*R2) + cellA[k])*128 + n];
                float* pB = &poolOut[((size_t)((k*B + bb)*R2) + cellB[k])*128 + n];
                atomicAdd(pA,     v0.x); atomicAdd(pA + 1, v0.y);
                atomicAdd(pB,     v1.x); atomicAdd(pB + 1, v1.y);
                if (n == 0) {
                    atomicAdd(&cnt[(k*B + bb)*R2 + cellA[k]], 1.0f);
                    atomicAdd(&cnt[(k*B + bb)*R2 + cellB[k]], 1.0f);
                }
            }
        }
    }
}

// ---------------- utility kernels ----------------
__global__ void k_pool_neg_inf(float* __restrict__ pool) {
    int i = blockIdx.x * blockDim.x + threadIdx.x;
    if (i < POOL_N / 4) {
        int4 v; v.x = v.y = v.z = v.w = 0xFF800000;
        ((int4*)pool)[i] = v;
    }
}
__global__ void k_zero(float* __restrict__ pool) {
    int i = blockIdx.x * blockDim.x + threadIdx.x;
    if (i < POOL_N / 4) {
        float4 z; z.x = z.y = z.z = z.w = 0.0f;
        ((float4*)pool)[i] = z;
    }
    if (i < CNT_N) g_cnt[i] = 0.0f;
}
__global__ void k_finalize(const float* __restrict__ pool, float* __restrict__ out) {
    int i = blockIdx.x * blockDim.x + threadIdx.x;
    if (i >= POOL_N) return;
    int cell = i & (R2 - 1);
    int f    = (i >> 14) & 127;
    int kb   = i >> 21;
    float cnt = g_cnt[kb * R2 + cell];
    out[i] = pool[(size_t)(kb * R2 + cell) * 128 + f] / fmaxf(cnt, 1.0f);
}

// ---------------- host orchestration ----------------
extern "C" void kernel_launch(void* const* d_in, const int* in_sizes, int n_in,
                              void* d_out, int out_size) {
    const float* p        = (const float*)d_in[0];
    const float* fc_pos_W = (const float*)d_in[1];
    const float* fc_pos_b = (const float*)d_in[2];
    const float* bW0      = (const float*)d_in[3];
    const float* bb0      = (const float*)d_in[4];
    const float* bW1      = (const float*)d_in[5];
    const float* bb1      = (const float*)d_in[6];
    const float* bWs      = (const float*)d_in[7];
    const float* fc_c_W   = (const float*)d_in[8];
    const float* fc_c_b   = (const float*)d_in[9];
    float* out = (float*)d_out;

    float* gnet = nullptr; cudaGetSymbolAddress((void**)&gnet, g_net);
    float* pA   = nullptr; cudaGetSymbolAddress((void**)&pA,   g_poolA);
    float* pB   = nullptr; cudaGetSymbolAddress((void**)&pB,   g_poolB);
    float* gcnt = nullptr; cudaGetSymbolAddress((void**)&gcnt, g_cnt);
    __nv_bfloat16* wt = nullptr; cudaGetSymbolAddress((void**)&wt, g_wt);

    cudaFuncSetAttribute(k_block<1, true >, cudaFuncAttributeMaxDynamicSharedMemorySize, FSMEM);
    cudaFuncSetAttribute(k_block<2, true >, cudaFuncAttributeMaxDynamicSharedMemorySize, FSMEM);
    cudaFuncSetAttribute(k_block<2, false>, cudaFuncAttributeMaxDynamicSharedMemorySize, FSMEM);
    cudaFuncSetAttribute(k_fcc,             cudaFuncAttributeMaxDynamicSharedMemorySize, FC_SMEM);

    const int TPB = 256;
    const int GG  = BT / 128;   // 512
    const int RG  = POOL_N / 4 / TPB;

    k_index<<<BT / TPB, TPB>>>(p);
    k_wsplit<<<(425984 + TPB - 1) / TPB, TPB>>>(bW0, bW1, bWs, fc_c_W);

    auto W0hi = [&](int b){ return wt + (size_t)b * 65536; };
    auto W0lo = [&](int b){ return wt + (size_t)b * 65536 + 32768; };
    auto W1hi = [&](int b){ return wt + 327680 + (size_t)b * 32768; };
    auto W1lo = [&](int b){ return wt + 327680 + (size_t)b * 32768 + 16384; };
    auto WShi = [&](int b){ return wt + 491520 + (size_t)b * 65536; };
    auto WSlo = [&](int b){ return wt + 491520 + (size_t)b * 65536 + 32768; };
    const __nv_bfloat16* FChi = wt + 819200;
    const __nv_bfloat16* FClo = wt + 819200 + 16384;

    // block 0 (fcpos A) -> net, scatter to poolA
    k_pool_neg_inf<<<RG, TPB>>>(pA);
    k_block<1, true><<<GG, TPB, FSMEM>>>(nullptr, p, fc_pos_W, fc_pos_b, nullptr, pA,
                                         W0hi(0), W0lo(0), W1hi(0), W1lo(0), WShi(0), WSlo(0),
                                         bb0, bb1, gnet);

    float* pin  = pA;
    float* pout = pB;
    for (int blk = 1; blk < 5; blk++) {
        if (blk < 4) {
            k_pool_neg_inf<<<RG, TPB>>>(pout);
            k_block<2, true><<<GG, TPB, FSMEM>>>(gnet, nullptr, nullptr, nullptr, pin, pout,
                                                 W0hi(blk), W0lo(blk), W1hi(blk), W1lo(blk),
                                                 WShi(blk), WSlo(blk),
                                                 bb0 + blk*128, bb1 + blk*128, gnet);
        } else {
            k_block<2, false><<<GG, TPB, FSMEM>>>(gnet, nullptr, nullptr, nullptr, pin, nullptr,
                                                  W0hi(blk), W0lo(blk), W1hi(blk), W1lo(blk),
                                                  WShi(blk), WSlo(blk),
                                                  bb0 + blk*128, bb1 + blk*128, gnet);
        }
        float* tmp = pin; pin = pout; pout = tmp;
    }

    // fc_c with fused scatter-mean into poolA
    k_zero<<<RG, TPB>>>(pA);
    k_fcc<<<GG, TPB, FC_SMEM>>>(gnet, pA, gcnt, FChi, FClo, fc_c_b);

    k_finalize<<<(POOL_N + TPB - 1) / TPB, TPB>>>(pA, out);
}